// round 5
// baseline (speedup 1.0000x reference)
#include <cuda_runtime.h>

#define NB    4
#define NPTS  8192
#define TPB   128
#define TQ    4
#define QB    (TPB*TQ)        // 512 queries per block
#define MT    1024            // targets per block (float4 units == points)
#define NPAIRS (NB*NPTS/2)    // 16384 target pairs per array

// Scratch (no allocations allowed):
__device__ float4   g_prepA[NB*NPTS];   // prepped array1 as targets
__device__ float4   g_prepB[NB*NPTS];   // prepped array2 as targets
__device__ unsigned g_enc1[NB*NPTS];    // encoded min(e) for dist1 (array1 queries)
__device__ unsigned g_enc2[NB*NPTS];    // encoded min(e) for dist2 (array2 queries)
__device__ float    g_part[128];

__device__ __forceinline__ unsigned long long pk2(float lo, float hi) {
    unsigned long long r;
    asm("mov.b64 %0, {%1,%2};" : "=l"(r) : "f"(lo), "f"(hi));
    return r;
}
// Order-preserving float->uint encoding (handles negatives) for atomicMin.
__device__ __forceinline__ unsigned fenc(float f) {
    unsigned b = __float_as_uint(f);
    return b ^ ((b & 0x80000000u) ? 0xFFFFFFFFu : 0x80000000u);
}
__device__ __forceinline__ float fdec(unsigned u) {
    unsigned b = (u & 0x80000000u) ? (u ^ 0x80000000u) : ~u;
    return __uint_as_float(b);
}

// Pack targets pair-interleaved AND init matching enc array to +inf.
// blockIdx.y selects which array. For pair p (points 2p,2p+1):
//   dst[2p]   = (-x0,-x1,-y0,-y1)
//   dst[2p+1] = (-z0,-z1, h0, h1)   with h = 0.5*(x^2+y^2+z^2)
__global__ void prep_kernel(const float* __restrict__ a1, const float* __restrict__ a2) {
    int which = blockIdx.y;
    const float* src = which ? a2      : a1;
    float4*      dst = which ? g_prepB : g_prepA;
    unsigned*    enc = which ? g_enc2  : g_enc1;
    int p = blockIdx.x * blockDim.x + threadIdx.x;
    const float* s = src + p * 6;   // batch boundaries are pair-aligned
    float x0 = s[0], y0 = s[1], z0 = s[2];
    float x1 = s[3], y1 = s[4], z1 = s[5];
    float h0 = 0.5f * (x0*x0 + y0*y0 + z0*z0);
    float h1 = 0.5f * (x1*x1 + y1*y1 + z1*z1);
    dst[2*p    ] = make_float4(-x0, -x1, -y0, -y1);
    dst[2*p + 1] = make_float4(-z0, -z1,  h0,  h1);
    enc[2*p    ] = 0xFFFFFFFFu;
    enc[2*p + 1] = 0xFFFFFFFFu;
}

// Fused both directions; single wave: grid (16, 8, 8) = 1024 CTAs.
// blockIdx.z = (batch<<1)|dir. dir=0: q=array1 vs g_prepB; dir=1: q=array2 vs g_prepA.
__global__ __launch_bounds__(TPB) void pass_kernel(const float* __restrict__ q1,
                                                   const float* __restrict__ q2) {
    int dir = blockIdx.z & 1;
    int b   = blockIdx.z >> 1;
    const float*  qraw   = dir ? q2      : q1;
    const float4* tp     = dir ? g_prepA : g_prepB;
    unsigned*     encOut = dir ? g_enc2  : g_enc1;

    int q0 = b * NPTS + blockIdx.x * QB;

    __shared__ float4 sh[MT];   // 16 KB: 512 target-pairs * 2 float4

    const float4* gsrc = tp + b * NPTS + blockIdx.y * MT;
    for (int i = threadIdx.x; i < MT; i += TPB) sh[i] = gsrc[i];

    unsigned long long X2[TQ], Y2[TQ], Z2[TQ];
    float mnlo[TQ], mnhi[TQ];
#pragma unroll
    for (int k = 0; k < TQ; k++) {
        int qg = q0 + threadIdx.x + k * TPB;
        float x = qraw[3*qg], y = qraw[3*qg+1], z = qraw[3*qg+2];
        X2[k] = pk2(x, x); Y2[k] = pk2(y, y); Z2[k] = pk2(z, z);
        mnlo[k] = __int_as_float(0x7f800000);   // +inf
        mnhi[k] = __int_as_float(0x7f800000);
    }
    __syncthreads();

#pragma unroll 2
    for (int p = 0; p < MT / 2; ++p) {
        float4 A  = sh[2*p];
        float4 Bv = sh[2*p + 1];
        unsigned long long NX = pk2(A.x,  A.y);
        unsigned long long NY = pk2(A.z,  A.w);
        unsigned long long NZ = pk2(Bv.x, Bv.y);
        unsigned long long H  = pk2(Bv.z, Bv.w);
#pragma unroll
        for (int k = 0; k < TQ; k++) {
            float lo, hi;
            // e = h - (xq*xt + yq*yt + zq*zt), two targets per packed op
            asm("{\n\t.reg .b64 t;\n\t"
                "fma.rn.f32x2 t, %2, %3, %4;\n\t"
                "fma.rn.f32x2 t, %5, %6, t;\n\t"
                "fma.rn.f32x2 t, %7, %8, t;\n\t"
                "mov.b64 {%0,%1}, t;\n\t}"
                : "=f"(lo), "=f"(hi)
                : "l"(Z2[k]), "l"(NZ), "l"(H),
                  "l"(Y2[k]), "l"(NY),
                  "l"(X2[k]), "l"(NX));
            mnlo[k] = fminf(mnlo[k], lo);   // independent alu-pipe chains
            mnhi[k] = fminf(mnhi[k], hi);
        }
    }

#pragma unroll
    for (int k = 0; k < TQ; k++)
        atomicMin(&encOut[q0 + threadIdx.x + k * TPB],
                  fenc(fminf(mnlo[k], mnhi[k])));
}

// dist_point = a^2 + 2*e = 2*(h + e). h lives in g_prep*[2p+1].z/.w (coalesced).
// 128 blocks x 128 threads; warp-shuffle tree (deterministic).
__global__ void reduce1_kernel() {
    int blk = blockIdx.x;                       // 0..127
    const float4*   pr  = (blk & 64) ? g_prepB : g_prepA;
    const unsigned* enc = (blk & 64) ? g_enc2  : g_enc1;
    int base = (blk & 63) * 256;                // 256 pairs per block
    int t = threadIdx.x;

    float s = 0.f;
#pragma unroll
    for (int i = 0; i < 2; i++) {
        int p = base + t + i * 128;
        float4 hv = pr[2*p + 1];
        s += (hv.z + fdec(enc[2*p])) + (hv.w + fdec(enc[2*p + 1]));
    }
#pragma unroll
    for (int o = 16; o > 0; o >>= 1)
        s += __shfl_down_sync(0xFFFFFFFFu, s, o);

    __shared__ float ws[4];
    if ((t & 31) == 0) ws[t >> 5] = s;
    __syncthreads();
    if (t == 0) g_part[blk] = (ws[0] + ws[1]) + (ws[2] + ws[3]);
}

__global__ void reduce2_kernel(float* __restrict__ out) {
    float s = g_part[threadIdx.x] + g_part[threadIdx.x + 64];
#pragma unroll
    for (int o = 16; o > 0; o >>= 1)
        s += __shfl_down_sync(0xFFFFFFFFu, s, o);
    __shared__ float ws[2];
    if ((threadIdx.x & 31) == 0) ws[threadIdx.x >> 5] = s;
    __syncthreads();
    // dist used h (=a^2/2): multiply by 2; then / (B*N)
    if (threadIdx.x == 0) out[0] = (ws[0] + ws[1]) * (2.0f / (float)(NB * NPTS));
}

extern "C" void kernel_launch(void* const* d_in, const int* in_sizes, int n_in,
                              void* d_out, int out_size) {
    const float* a1 = (const float*)d_in[0];   // array1 [4,8192,3]
    const float* a2 = (const float*)d_in[1];   // array2 [4,8192,3]
    float* out = (float*)d_out;

    dim3 pgrid(NPAIRS / 256, 2);
    prep_kernel<<<pgrid, 256>>>(a1, a2);        // both preps + enc init

    dim3 grid(NPTS / QB, NPTS / MT, 2 * NB);    // (16, 8, 8) = 1024 blocks: one wave
    pass_kernel<<<grid, TPB>>>(a1, a2);

    reduce1_kernel<<<128, 128>>>();
    reduce2_kernel<<<1, 64>>>(out);
}